// round 1
// baseline (speedup 1.0000x reference)
#include <cuda_runtime.h>

#define Nn 50000
#define Hh 128
#define Ee 500000
#define TK 16
#define LDP 132   // padded pitch for shared tiles (conflict mitigation, 16B-aligned)

// Scratch (device globals: no allocation allowed)
__device__ float g_aggr[(size_t)Nn * Hh];
__device__ float g_h1[(size_t)Nn * Hh];

// ---------------------------------------------------------------------------
// Zero the aggregation buffer (float4 stores)
// ---------------------------------------------------------------------------
__global__ void zero_kernel() {
    size_t i = (size_t)blockIdx.x * blockDim.x + threadIdx.x;
    if (i < (size_t)Nn * Hh / 4) {
        reinterpret_cast<float4*>(g_aggr)[i] = make_float4(0.f, 0.f, 0.f, 0.f);
    }
}

// ---------------------------------------------------------------------------
// Scatter-add: one warp per edge. Each lane moves 4 contiguous floats.
// aggr[dst] += x[src], dst = edge[0][e], src = edge[1][e]
// Uses vectorized f32 reduction (sm_90+): 4x fewer L2 atomic ops.
// ---------------------------------------------------------------------------
__global__ void scatter_kernel(const float* __restrict__ x,
                               const int* __restrict__ edge) {
    int e = blockIdx.x * 8 + (threadIdx.x >> 5);
    if (e >= Ee) return;
    int lane = threadIdx.x & 31;
    int dst = __ldg(edge + e);        // edge_index[0][e]
    int src = __ldg(edge + Ee + e);   // edge_index[1][e]
    float4 v = *reinterpret_cast<const float4*>(x + (size_t)src * Hh + lane * 4);
    float* p = g_aggr + (size_t)dst * Hh + lane * 4;
    asm volatile("red.global.add.v4.f32 [%0], {%1, %2, %3, %4};"
                 :: "l"(p), "f"(v.x), "f"(v.y), "f"(v.z), "f"(v.w)
                 : "memory");
}

// ---------------------------------------------------------------------------
// Tiled SGEMM: C[M,128] = act( A0 @ W0^T + (A1 @ (W1a+W1b)^T) + biases )
//   - weights are [128,128] row-major torch-Linear style: out=x@W.T
//   - 128x128 output tile per block, TK=16 k-chunk, 256 threads, 8x8 microtile
//   - second segment (A1) optional; W1b optionally added into W1a at load
// ---------------------------------------------------------------------------
__global__ __launch_bounds__(256, 2) void gemm_kernel(
    const float* __restrict__ A0, const float* __restrict__ W0,
    const float* __restrict__ A1, const float* __restrict__ W1a,
    const float* __restrict__ W1b,
    const float* __restrict__ ba, const float* __restrict__ bb,
    const float* __restrict__ bc,
    float* __restrict__ C, int M, int do_relu)
{
    __shared__ __align__(16) float As[TK * LDP];
    __shared__ __align__(16) float Bs[TK * LDP];

    const int tid = threadIdx.x;
    const int ty = tid >> 4;        // 0..15
    const int tx = tid & 15;        // 0..15
    const int m0 = ty * 8;
    const int n0 = tx * 8;
    const int bm = blockIdx.x * 128;

    float acc[8][8];
    #pragma unroll
    for (int i = 0; i < 8; i++)
        #pragma unroll
        for (int j = 0; j < 8; j++) acc[i][j] = 0.f;

    const int nseg = (A1 != nullptr) ? 2 : 1;
    for (int seg = 0; seg < nseg; seg++) {
        const float* A  = seg ? A1 : A0;
        const float* Wa = seg ? W1a : W0;
        const float* Wb = seg ? W1b : nullptr;

        for (int kk = 0; kk < 128; kk += TK) {
            // ---- load A tile (transposed into As[k][m]) + B tile Bs[k][n] ----
            #pragma unroll
            for (int q = 0; q < 2; q++) {
                int l = q * 256 + tid;     // 0..511
                int row = l >> 2;          // 0..127
                int kq = (l & 3) * 4;      // 0,4,8,12

                float4 va = make_float4(0.f, 0.f, 0.f, 0.f);
                if (bm + row < M)
                    va = *reinterpret_cast<const float4*>(
                        A + (size_t)(bm + row) * 128 + kk + kq);
                As[(kq + 0) * LDP + row] = va.x;
                As[(kq + 1) * LDP + row] = va.y;
                As[(kq + 2) * LDP + row] = va.z;
                As[(kq + 3) * LDP + row] = va.w;

                float4 vb = *reinterpret_cast<const float4*>(
                    Wa + (size_t)row * 128 + kk + kq);
                if (Wb) {
                    float4 v2 = *reinterpret_cast<const float4*>(
                        Wb + (size_t)row * 128 + kk + kq);
                    vb.x += v2.x; vb.y += v2.y; vb.z += v2.z; vb.w += v2.w;
                }
                Bs[(kq + 0) * LDP + row] = vb.x;
                Bs[(kq + 1) * LDP + row] = vb.y;
                Bs[(kq + 2) * LDP + row] = vb.z;
                Bs[(kq + 3) * LDP + row] = vb.w;
            }
            __syncthreads();

            // ---- compute ----
            #pragma unroll
            for (int k = 0; k < TK; k++) {
                float a[8], b[8];
                float4 t;
                t = *reinterpret_cast<float4*>(&As[k * LDP + m0]);
                a[0] = t.x; a[1] = t.y; a[2] = t.z; a[3] = t.w;
                t = *reinterpret_cast<float4*>(&As[k * LDP + m0 + 4]);
                a[4] = t.x; a[5] = t.y; a[6] = t.z; a[7] = t.w;
                t = *reinterpret_cast<float4*>(&Bs[k * LDP + n0]);
                b[0] = t.x; b[1] = t.y; b[2] = t.z; b[3] = t.w;
                t = *reinterpret_cast<float4*>(&Bs[k * LDP + n0 + 4]);
                b[4] = t.x; b[5] = t.y; b[6] = t.z; b[7] = t.w;
                #pragma unroll
                for (int i = 0; i < 8; i++)
                    #pragma unroll
                    for (int j = 0; j < 8; j++)
                        acc[i][j] = fmaf(a[i], b[j], acc[i][j]);
            }
            __syncthreads();
        }
    }

    // ---- epilogue: bias + optional relu, float4 stores ----
    float bias[8];
    #pragma unroll
    for (int j = 0; j < 8; j++) {
        float s = 0.f;
        if (ba) s += __ldg(ba + n0 + j);
        if (bb) s += __ldg(bb + n0 + j);
        if (bc) s += __ldg(bc + n0 + j);
        bias[j] = s;
    }
    #pragma unroll
    for (int i = 0; i < 8; i++) {
        int row = bm + m0 + i;
        if (row < M) {
            float v[8];
            #pragma unroll
            for (int j = 0; j < 8; j++) {
                float x = acc[i][j] + bias[j];
                v[j] = do_relu ? fmaxf(x, 0.f) : x;
            }
            float4 o0 = make_float4(v[0], v[1], v[2], v[3]);
            float4 o1 = make_float4(v[4], v[5], v[6], v[7]);
            *reinterpret_cast<float4*>(C + (size_t)row * 128 + n0)     = o0;
            *reinterpret_cast<float4*>(C + (size_t)row * 128 + n0 + 4) = o1;
        }
    }
}

// ---------------------------------------------------------------------------
// Launch: only the h_a branch matters — h_b in the reference is dead code.
// out = (relu(aggr_ba @ wl.T + x_a @ (w0+w1).T + biases)) @ out_w.T + out_b
// ---------------------------------------------------------------------------
extern "C" void kernel_launch(void* const* d_in, const int* in_sizes, int n_in,
                              void* d_out, int out_size) {
    const float* x_a     = (const float*)d_in[0];
    const int*   edge_ba = (const int*)d_in[3];
    const float* c1_w0_w = (const float*)d_in[10];
    const float* c1_w0_b = (const float*)d_in[11];
    const float* c1_wl_w = (const float*)d_in[12];
    const float* c1_wl_b = (const float*)d_in[13];
    const float* c1_w1_w = (const float*)d_in[14];
    const float* c1_w1_b = (const float*)d_in[15];
    const float* out_w   = (const float*)d_in[16];
    const float* out_b   = (const float*)d_in[17];
    float* out = (float*)d_out;

    float *aggr_p = nullptr, *h1_p = nullptr;
    cudaGetSymbolAddress((void**)&aggr_p, g_aggr);
    cudaGetSymbolAddress((void**)&h1_p, g_h1);

    // 1) zero aggr
    zero_kernel<<<((size_t)Nn * Hh / 4 + 255) / 256, 256>>>();

    // 2) scatter-add over edge_ba
    scatter_kernel<<<(Ee + 7) / 8, 256>>>(x_a, edge_ba);

    const int grid = (Nn + 127) / 128;  // 391 blocks

    // 3) h1 = relu(aggr @ wl.T + x_a @ (w0+w1).T + (bl+b0+b1))
    gemm_kernel<<<grid, 256>>>(aggr_p, c1_wl_w,
                               x_a, c1_w0_w, c1_w1_w,
                               c1_wl_b, c1_w0_b, c1_w1_b,
                               h1_p, Nn, 1);

    // 4) out = h1 @ out_w.T + out_b
    gemm_kernel<<<grid, 256>>>(h1_p, out_w,
                               nullptr, nullptr, nullptr,
                               out_b, nullptr, nullptr,
                               out, Nn, 0);
}

// round 2
// speedup vs baseline: 1.1200x; 1.1200x over previous
#include <cuda_runtime.h>

#define Nn 50000
#define Hh 128
#define Ee 500000
#define TK 16
#define LDP 132   // padded pitch for shared tiles
#define NBLK 196  // ceil(Nn/256)

typedef unsigned long long u64;

// Scratch (device globals: no allocation allowed)
__device__ float g_aggr[(size_t)Nn * Hh];
__device__ float g_h1[(size_t)Nn * Hh];
__device__ int   g_cnt[Nn];    // per-node degree
__device__ int   g_cur[Nn];    // fill cursors
__device__ int   g_base[Nn];   // CSR row offsets (exclusive scan of cnt)
__device__ int   g_srcs[Ee];   // bucketed source indices
__device__ int   g_bs[NBLK];   // block sums for scan

// ---------------------------------------------------------------------------
// CSR build: count -> scan -> fill
// ---------------------------------------------------------------------------
__global__ void zero_cnt_kernel() {
    int i = blockIdx.x * 256 + threadIdx.x;
    if (i < Nn) g_cnt[i] = 0;
}

__global__ void count_kernel(const int* __restrict__ edge) {
    int e = blockIdx.x * 256 + threadIdx.x;
    if (e < Ee) atomicAdd(&g_cnt[__ldg(edge + e)], 1);
}

__device__ __forceinline__ int warp_scan_incl(int v, int lane) {
    #pragma unroll
    for (int o = 1; o < 32; o <<= 1) {
        int n = __shfl_up_sync(0xffffffffu, v, o);
        if (lane >= o) v += n;
    }
    return v;
}

__global__ void scan1_kernel() {
    __shared__ int ws[8];
    int t = threadIdx.x, lane = t & 31, wid = t >> 5;
    int i = blockIdx.x * 256 + t;
    int v = (i < Nn) ? g_cnt[i] : 0;
    int inc = warp_scan_incl(v, lane);
    if (lane == 31) ws[wid] = inc;
    __syncthreads();
    if (wid == 0) {
        int wv = (lane < 8) ? ws[lane] : 0;
        wv = warp_scan_incl(wv, lane);
        if (lane < 8) ws[lane] = wv;
    }
    __syncthreads();
    int off = (wid > 0) ? ws[wid - 1] : 0;
    if (i < Nn) g_base[i] = off + inc - v;        // exclusive within block
    if (t == 255) g_bs[blockIdx.x] = off + inc;   // block total
}

__global__ void scan2_kernel() {   // single block, scans the 196 block sums
    __shared__ int ws[8];
    int t = threadIdx.x, lane = t & 31, wid = t >> 5;
    int v = (t < NBLK) ? g_bs[t] : 0;
    int inc = warp_scan_incl(v, lane);
    if (lane == 31) ws[wid] = inc;
    __syncthreads();
    if (wid == 0) {
        int wv = (lane < 8) ? ws[lane] : 0;
        wv = warp_scan_incl(wv, lane);
        if (lane < 8) ws[lane] = wv;
    }
    __syncthreads();
    int off = (wid > 0) ? ws[wid - 1] : 0;
    if (t < NBLK) g_bs[t] = off + inc - v;        // exclusive block offsets
}

__global__ void scan3_kernel() {
    int i = blockIdx.x * 256 + threadIdx.x;
    if (i < Nn) {
        g_base[i] += g_bs[blockIdx.x];
        g_cur[i] = 0;
    }
}

__global__ void fill_kernel(const int* __restrict__ edge) {
    int e = blockIdx.x * 256 + threadIdx.x;
    if (e < Ee) {
        int dst = __ldg(edge + e);        // edge_index[0][e]
        int src = __ldg(edge + Ee + e);   // edge_index[1][e]
        int pos = g_base[dst] + atomicAdd(&g_cur[dst], 1);
        g_srcs[pos] = src;
    }
}

// ---------------------------------------------------------------------------
// Gather-reduce: one warp per node, 4 floats per lane, fp32 register sums.
// ---------------------------------------------------------------------------
__global__ void aggregate_kernel(const float* __restrict__ x) {
    int n = blockIdx.x * 8 + (threadIdx.x >> 5);
    if (n >= Nn) return;
    int lane = threadIdx.x & 31;
    int base = g_base[n];
    int deg  = g_cnt[n];
    float4 acc = make_float4(0.f, 0.f, 0.f, 0.f);
    for (int d = 0; d < deg; d++) {
        int src = __ldg(g_srcs + base + d);
        float4 v = *reinterpret_cast<const float4*>(x + (size_t)src * Hh + lane * 4);
        acc.x += v.x; acc.y += v.y; acc.z += v.z; acc.w += v.w;
    }
    *reinterpret_cast<float4*>(g_aggr + (size_t)n * Hh + lane * 4) = acc;
}

// ---------------------------------------------------------------------------
// f32x2 packed-FMA helpers
// ---------------------------------------------------------------------------
__device__ __forceinline__ u64 pack_dup(float v) {
    u64 r;
    asm("mov.b64 %0, {%1,%1};" : "=l"(r) : "f"(v));
    return r;
}
__device__ __forceinline__ void fma2(u64& acc, u64 a, u64 b) {
    asm("fma.rn.f32x2 %0, %1, %2, %0;" : "+l"(acc) : "l"(a), "l"(b));
}

// ---------------------------------------------------------------------------
// Tiled SGEMM with packed f32x2 FMAs:
//   C[M,128] = act( A0 @ W0^T + (A1 @ (W1a+W1b)^T) + biases )
//   128x128 tile / block, TK=16, 256 threads, 8x8 microtile (paired along m)
// ---------------------------------------------------------------------------
__global__ __launch_bounds__(256, 2) void gemm_kernel(
    const float* __restrict__ A0, const float* __restrict__ W0,
    const float* __restrict__ A1, const float* __restrict__ W1a,
    const float* __restrict__ W1b,
    const float* __restrict__ ba, const float* __restrict__ bb,
    const float* __restrict__ bc,
    float* __restrict__ C, int M, int do_relu)
{
    __shared__ __align__(16) float As[TK * LDP];
    __shared__ __align__(16) float Bs[TK * LDP];

    const int tid = threadIdx.x;
    const int ty = tid >> 4;        // 0..15
    const int tx = tid & 15;        // 0..15
    const int m0 = ty * 8;
    const int n0 = tx * 8;
    const int bm = blockIdx.x * 128;

    // acc2[p][j] = ( C[m0+2p][n0+j], C[m0+2p+1][n0+j] )
    u64 acc2[4][8];
    #pragma unroll
    for (int p = 0; p < 4; p++)
        #pragma unroll
        for (int j = 0; j < 8; j++) acc2[p][j] = 0ull;

    const int nseg = (A1 != nullptr) ? 2 : 1;
    for (int seg = 0; seg < nseg; seg++) {
        const float* A  = seg ? A1 : A0;
        const float* Wa = seg ? W1a : W0;
        const float* Wb = seg ? W1b : nullptr;

        for (int kk = 0; kk < 128; kk += TK) {
            // ---- stage A tile (k-major: As[k][m]) and B tile (Bs[k][n]) ----
            #pragma unroll
            for (int q = 0; q < 2; q++) {
                int l = q * 256 + tid;     // 0..511
                int row = l >> 2;          // 0..127
                int kq = (l & 3) * 4;      // 0,4,8,12

                float4 va = make_float4(0.f, 0.f, 0.f, 0.f);
                if (bm + row < M)
                    va = *reinterpret_cast<const float4*>(
                        A + (size_t)(bm + row) * 128 + kk + kq);
                As[(kq + 0) * LDP + row] = va.x;
                As[(kq + 1) * LDP + row] = va.y;
                As[(kq + 2) * LDP + row] = va.z;
                As[(kq + 3) * LDP + row] = va.w;

                float4 vb = *reinterpret_cast<const float4*>(
                    Wa + (size_t)row * 128 + kk + kq);
                if (Wb) {
                    float4 v2 = *reinterpret_cast<const float4*>(
                        Wb + (size_t)row * 128 + kk + kq);
                    vb.x += v2.x; vb.y += v2.y; vb.z += v2.z; vb.w += v2.w;
                }
                Bs[(kq + 0) * LDP + row] = vb.x;
                Bs[(kq + 1) * LDP + row] = vb.y;
                Bs[(kq + 2) * LDP + row] = vb.z;
                Bs[(kq + 3) * LDP + row] = vb.w;
            }
            __syncthreads();

            // ---- compute: packed pairs along m ----
            #pragma unroll
            for (int k = 0; k < TK; k++) {
                // a pairs load directly as 64-bit from shared
                ulonglong2 a01 = *reinterpret_cast<ulonglong2*>(&As[k * LDP + m0]);
                ulonglong2 a23 = *reinterpret_cast<ulonglong2*>(&As[k * LDP + m0 + 4]);
                u64 a2[4] = { a01.x, a01.y, a23.x, a23.y };

                float4 t0 = *reinterpret_cast<float4*>(&Bs[k * LDP + n0]);
                float4 t1 = *reinterpret_cast<float4*>(&Bs[k * LDP + n0 + 4]);
                u64 b2[8] = { pack_dup(t0.x), pack_dup(t0.y),
                              pack_dup(t0.z), pack_dup(t0.w),
                              pack_dup(t1.x), pack_dup(t1.y),
                              pack_dup(t1.z), pack_dup(t1.w) };

                #pragma unroll
                for (int p = 0; p < 4; p++)
                    #pragma unroll
                    for (int j = 0; j < 8; j++)
                        fma2(acc2[p][j], a2[p], b2[j]);
            }
            __syncthreads();
        }
    }

    // ---- epilogue: bias + optional relu, float4 stores (row pairs) ----
    float bias[8];
    #pragma unroll
    for (int j = 0; j < 8; j++) {
        float s = 0.f;
        if (ba) s += __ldg(ba + n0 + j);
        if (bb) s += __ldg(bb + n0 + j);
        if (bc) s += __ldg(bc + n0 + j);
        bias[j] = s;
    }
    #pragma unroll
    for (int p = 0; p < 4; p++) {
        float vlo[8], vhi[8];
        #pragma unroll
        for (int j = 0; j < 8; j++) {
            float2 f = *reinterpret_cast<float2*>(&acc2[p][j]);
            float xlo = f.x + bias[j];
            float xhi = f.y + bias[j];
            vlo[j] = do_relu ? fmaxf(xlo, 0.f) : xlo;
            vhi[j] = do_relu ? fmaxf(xhi, 0.f) : xhi;
        }
        int rlo = bm + m0 + 2 * p;
        int rhi = rlo + 1;
        if (rlo < M) {
            *reinterpret_cast<float4*>(C + (size_t)rlo * 128 + n0) =
                make_float4(vlo[0], vlo[1], vlo[2], vlo[3]);
            *reinterpret_cast<float4*>(C + (size_t)rlo * 128 + n0 + 4) =
                make_float4(vlo[4], vlo[5], vlo[6], vlo[7]);
        }
        if (rhi < M) {
            *reinterpret_cast<float4*>(C + (size_t)rhi * 128 + n0) =
                make_float4(vhi[0], vhi[1], vhi[2], vhi[3]);
            *reinterpret_cast<float4*>(C + (size_t)rhi * 128 + n0 + 4) =
                make_float4(vhi[4], vhi[5], vhi[6], vhi[7]);
        }
    }
}

// ---------------------------------------------------------------------------
// Launch: only the h_a branch matters — h_b in the reference is dead code.
// out = (relu(aggr_ba @ wl.T + x_a @ (w0+w1).T + biases)) @ out_w.T + out_b
// ---------------------------------------------------------------------------
extern "C" void kernel_launch(void* const* d_in, const int* in_sizes, int n_in,
                              void* d_out, int out_size) {
    const float* x_a     = (const float*)d_in[0];
    const int*   edge_ba = (const int*)d_in[3];
    const float* c1_w0_w = (const float*)d_in[10];
    const float* c1_w0_b = (const float*)d_in[11];
    const float* c1_wl_w = (const float*)d_in[12];
    const float* c1_wl_b = (const float*)d_in[13];
    const float* c1_w1_w = (const float*)d_in[14];
    const float* c1_w1_b = (const float*)d_in[15];
    const float* out_w   = (const float*)d_in[16];
    const float* out_b   = (const float*)d_in[17];
    float* out = (float*)d_out;

    float *aggr_p = nullptr, *h1_p = nullptr;
    cudaGetSymbolAddress((void**)&aggr_p, g_aggr);
    cudaGetSymbolAddress((void**)&h1_p, g_h1);

    const int egrid = (Ee + 255) / 256;   // 1954
    const int ngrid = NBLK;               // 196

    // CSR build
    zero_cnt_kernel<<<ngrid, 256>>>();
    count_kernel<<<egrid, 256>>>(edge_ba);
    scan1_kernel<<<ngrid, 256>>>();
    scan2_kernel<<<1, 256>>>();
    scan3_kernel<<<ngrid, 256>>>();
    fill_kernel<<<egrid, 256>>>(edge_ba);

    // Gather-reduce into aggr (no zero pass needed)
    aggregate_kernel<<<(Nn + 7) / 8, 256>>>(x_a);

    const int grid = (Nn + 127) / 128;  // 391 blocks

    // h1 = relu(aggr @ wl.T + x_a @ (w0+w1).T + (bl+b0+b1))
    gemm_kernel<<<grid, 256>>>(aggr_p, c1_wl_w,
                               x_a, c1_w0_w, c1_w1_w,
                               c1_wl_b, c1_w0_b, c1_w1_b,
                               h1_p, Nn, 1);

    // out = h1 @ out_w.T + out_b
    gemm_kernel<<<grid, 256>>>(h1_p, out_w,
                               nullptr, nullptr, nullptr,
                               out_b, nullptr, nullptr,
                               out, Nn, 0);
}